// round 5
// baseline (speedup 1.0000x reference)
#include <cuda_runtime.h>
#include <cstdint>
#include <math.h>

// JeffressLinear: x (64,64,128,2) f32, delay_latent (31,1) f32, weight scalar
// out (64,64,128,31) f32 = 65MB.
//
// d = floor(relu(+-latent)) in 0..15 (frac=0 -> bernoulli dead), clamped per
// (n,c,i) by 63-argmax_t(x). LIF over shifted series -> spike masks.
// out[t,n,c,j] = w*(bit(m[c,0,d0],t)+bit(m[c,1,d1],t)).
//
// BOUND: v_t=(v_{t-1}+x_t)/2 <= max_t(x)·(1+64ulp). If row max < 0.999 no spike
// can fire for any shift -> output rows exactly 0.
//
// K1: compute clamp/flags (+ masks only if some row can spike) into scratch.
// K2: one block per (t,n), consecutive blocks write consecutive 15.9KB chunks
//     -> pure dense streaming stores (fast path), honest expansion otherwise.

namespace {

constexpr int T_ = 64;
constexpr int N_ = 64;
constexpr int Q_ = 256;        // 128 channels x 2 components per n
constexpr int D_ = 31;
constexpr int ROWPITCH = 133;  // 128 dup + 5 pad

__device__ unsigned g_mlo[N_][Q_][16];
__device__ unsigned g_mhi[N_][Q_][16];
__device__ int      g_clamp[N_][Q_];
__device__ int      g_flag[N_][4];

// ---------------- K1: per-(n, quarter) analysis ----------------
__global__ void __launch_bounds__(256) analyze_kernel(const float* __restrict__ x)
{
    __shared__ float xs[64 * ROWPITCH];   // 64 rows, duplicated to 128 cols
    __shared__ float smax[64];
    __shared__ int   sflag;

    const int tid = threadIdx.x;
    const int n   = blockIdx.x >> 2;
    const int qq  = blockIdx.x & 3;
    const int q0  = qq * 64;

    if (tid == 0) sflag = 0;

    // load 64 t x 64 q, transpose + duplicate
    const float* xb = x + (size_t)n * Q_ + q0;
#pragma unroll
    for (int k = 0; k < 16; ++k) {
        int idx = tid + k * 256;          // 0..4095
        int t = idx >> 6;
        int r = idx & 63;
        float v = xb[(size_t)t * (N_ * Q_) + r];
        xs[r * ROWPITCH + t]      = v;
        xs[r * ROWPITCH + 64 + t] = v;
    }
    __syncthreads();

    // per-row max + first-occurrence argmax
    if (tid < 64) {
        const float* row = xs + tid * ROWPITCH;
        float best = row[0];
        int bi = 0;
#pragma unroll
        for (int t = 1; t < T_; ++t) {
            float v = row[t];
            if (v > best) { best = v; bi = t; }
        }
        g_clamp[n][q0 + tid] = (T_ - 1) - bi;
        smax[tid] = best;
        if (best >= 0.999f) sflag = 1;    // benign race
    }
    __syncthreads();

    int f = sflag;
    if (tid == 0) g_flag[n][qq] = f;

    if (f) {  // some row may spike: compute all 1024 (row,d) LIF masks
#pragma unroll
        for (int k = 0; k < 4; ++k) {
            int run = tid + k * 256;      // 0..1023
            int d = run & 15;
            int r = run >> 4;
            const float* src = xs + r * ROWPITCH + (64 - d);
            unsigned lo = 0u, hi = 0u;
            float v = 0.0f;
#pragma unroll
            for (int t = 0; t < 32; ++t) {
                float xt = src[t];
                v = v + (xt - v) * 0.5f;          // exact reference order
                if (v >= 1.0f) { lo |= (1u << t); v = 0.0f; }
            }
#pragma unroll
            for (int t = 0; t < 32; ++t) {
                float xt = src[32 + t];
                v = v + (xt - v) * 0.5f;
                if (v >= 1.0f) { hi |= (1u << t); v = 0.0f; }
            }
            g_mlo[n][q0 + r][d] = lo;
            g_mhi[n][q0 + r][d] = hi;
        }
    }
}

// ---------------- K2: streaming writer, one block per (t,n) ----------------
__global__ void __launch_bounds__(256) write_kernel(
    const float* __restrict__ delay_latent,
    const float* __restrict__ wptr,
    float* __restrict__ out)
{
    const int tid = threadIdx.x;
    const int bid = blockIdx.x;
    const int t   = bid >> 6;
    const int n   = bid & 63;

    // uniform broadcast loads (L1/L2 hit)
    int f = g_flag[n][0] | g_flag[n][1] | g_flag[n][2] | g_flag[n][3];

    float* obase = out + (size_t)bid * 3968;   // (t*64+n)*128*31, contiguous chunk

    if (!f) {
        // fast path: dense zero-fill of 15.9KB, 248 threads x 4 float4
        if (tid < 248) {
            float4* p = reinterpret_cast<float4*>(obase) + tid * 4;
            const float4 z = make_float4(0.f, 0.f, 0.f, 0.f);
            p[0] = z; p[1] = z; p[2] = z; p[3] = z;
        }
        return;
    }

    // slow path: honest expansion from masks
    __shared__ int dt0[D_], dt1[D_];
    if (tid < D_) {
        float dl = delay_latent[tid];
        dt0[tid] = (int)floorf(fmaxf(dl, 0.0f));
        dt1[tid] = (int)floorf(fmaxf(-dl, 0.0f));
    }
    __syncthreads();

    const float w = *wptr;
    const bool hiHalf = (t >= 32);
    const int  sh = t & 31;

    if (tid < 248) {
#pragma unroll
        for (int k = 0; k < 16; ++k) {
            int cj = tid + k * 248;       // 0..3967
            int c = cj / 31;
            int j = cj - c * 31;
            int q0 = c * 2;
            int d0 = min(dt0[j], g_clamp[n][q0]);
            int d1 = min(dt1[j], g_clamp[n][q0 + 1]);
            unsigned m0 = hiHalf ? g_mhi[n][q0][d0]     : g_mlo[n][q0][d0];
            unsigned m1 = hiHalf ? g_mhi[n][q0 + 1][d1] : g_mlo[n][q0 + 1][d1];
            int s = (int)((m0 >> sh) & 1u) + (int)((m1 >> sh) & 1u);
            obase[cj] = (float)s * w;     // == s0*w + s1*w exactly for s in {0,1,2}
        }
    }
}

} // namespace

extern "C" void kernel_launch(void* const* d_in, const int* in_sizes, int n_in,
                              void* d_out, int out_size) {
    const float* x  = (const float*)d_in[0];   // (64,64,128,2)
    const float* dl = (const float*)d_in[1];   // (31,1)
    const float* w  = (const float*)d_in[2];   // scalar
    float* out = (float*)d_out;                // (64,64,128,31)
    analyze_kernel<<<256, 256>>>(x);
    write_kernel<<<4096, 256>>>(dl, w, out);
}

// round 6
// speedup vs baseline: 2.2663x; 2.2663x over previous
#include <cuda_runtime.h>
#include <cstdint>
#include <math.h>

// JeffressLinear: x (64,64,128,2) f32, delay_latent (31,1) f32, weight scalar
// out (64,64,128,31) f32 = 65MB.
//
// d = floor(relu(+-latent)) in 0..15 (frac=0 -> bernoulli dead), clamped per
// (n,c,i) by 63-argmax_t(x). LIF over shifted series -> spike masks.
// out[t,n,c,j] = w*(bit(m[c,0,d0],t)+bit(m[c,1,d1],t)).
//
// BOUND: v_t=(v_{t-1}+x_t)/2 (rounded) < 1 whenever all x<1, and more loosely
// v <= rowmax*(1+eps). Rows with max < 0.999 provably never spike (masks = 0,
// skipped). For other rows K1 computes masks HONESTLY; the per-(n,quarter)
// flag is the OR of ACTUAL spike bits (exact, not conservative).
// K2: flag==0 -> dense zero-fill stream; else honest mask expansion.

namespace {

constexpr int T_ = 64;
constexpr int N_ = 64;
constexpr int Q_ = 256;        // 128 channels x 2 components per n
constexpr int D_ = 31;
constexpr int ROWPITCH = 133;  // 128 dup + 5 pad

__device__ unsigned g_mlo[N_][Q_][16];
__device__ unsigned g_mhi[N_][Q_][16];
__device__ int      g_clamp[N_][Q_];
__device__ float    g_rowmax[N_][Q_];
__device__ int      g_flag[N_][4];     // OR of actual spike bits per quarter

// ---------------- K1: per-(n, quarter=64 rows) analysis ----------------
__global__ void __launch_bounds__(256) analyze_kernel(const float* __restrict__ x)
{
    __shared__ float    xs[64 * ROWPITCH];  // 64 rows, duplicated to 128 cols
    __shared__ float    smax[64];
    __shared__ unsigned sany[8];            // per-warp OR of spike bits

    const int tid = threadIdx.x;
    const int n   = blockIdx.x >> 2;
    const int qq  = blockIdx.x & 3;
    const int q0  = qq * 64;

    if (tid < 8) sany[tid] = 0u;

    // load 64 t x 64 q, transpose + duplicate rows to 128
    const float* xb = x + (size_t)n * Q_ + q0;
#pragma unroll
    for (int k = 0; k < 16; ++k) {
        int idx = tid + k * 256;            // 0..4095
        int t = idx >> 6;
        int r = idx & 63;
        float v = xb[(size_t)t * (N_ * Q_) + r];
        xs[r * ROWPITCH + t]      = v;
        xs[r * ROWPITCH + 64 + t] = v;
    }
    __syncthreads();

    // per-row max + first-occurrence argmax (64 threads, 1 row each)
    if (tid < 64) {
        const float* row = xs + tid * ROWPITCH;
        float best = row[0];
        int bi = 0;
#pragma unroll
        for (int t = 1; t < T_; ++t) {
            float v = row[t];
            if (v > best) { best = v; bi = t; }
        }
        g_clamp[n][q0 + tid]  = (T_ - 1) - bi;
        g_rowmax[n][q0 + tid] = best;
        smax[tid] = best;
    }
    __syncthreads();

    // LIF masks only for rows that could possibly spike (max >= 0.999);
    // warp covers 2 rows x 16 delays -> ~88% of warps skip entirely.
    unsigned myany = 0u;
#pragma unroll
    for (int k = 0; k < 4; ++k) {
        int run = tid + k * 256;            // 0..1023
        int d = run & 15;
        int r = run >> 4;
        if (smax[r] >= 0.999f) {
            const float* src = xs + r * ROWPITCH + (64 - d);
            unsigned lo = 0u, hi = 0u;
            float v = 0.0f;
#pragma unroll
            for (int t = 0; t < 32; ++t) {
                float xt = src[t];
                v = v + (xt - v) * 0.5f;     // exact reference arithmetic order
                if (v >= 1.0f) { lo |= (1u << t); v = 0.0f; }
            }
#pragma unroll
            for (int t = 0; t < 32; ++t) {
                float xt = src[32 + t];
                v = v + (xt - v) * 0.5f;
                if (v >= 1.0f) { hi |= (1u << t); v = 0.0f; }
            }
            g_mlo[n][q0 + r][d] = lo;
            g_mhi[n][q0 + r][d] = hi;
            myany = lo | hi;
        }
    }

    // exact flag: OR of actual spike bits in this quarter
#pragma unroll
    for (int off = 16; off >= 1; off >>= 1)
        myany |= __shfl_xor_sync(0xffffffffu, myany, off);
    if ((tid & 31) == 0 && myany) sany[tid >> 5] = myany;
    __syncthreads();
    if (tid == 0) {
        unsigned a = 0u;
#pragma unroll
        for (int i = 0; i < 8; ++i) a |= sany[i];
        g_flag[n][qq] = (a != 0u);
    }
}

// ---------------- K2: streaming writer, one block per (t,n) ----------------
__global__ void __launch_bounds__(256) write_kernel(
    const float* __restrict__ delay_latent,
    const float* __restrict__ wptr,
    float* __restrict__ out)
{
    const int tid = threadIdx.x;
    const int bid = blockIdx.x;
    const int t   = bid >> 6;
    const int n   = bid & 63;

    int f = g_flag[n][0] | g_flag[n][1] | g_flag[n][2] | g_flag[n][3];

    float* obase = out + (size_t)bid * 3968;   // contiguous 15.9KB chunk

    if (!f) {
        // fast path: no spike anywhere for this n -> dense zero-fill
        if (tid < 248) {
            float4* p = reinterpret_cast<float4*>(obase);
            const float4 z = make_float4(0.f, 0.f, 0.f, 0.f);
            p[tid]       = z;
            p[tid + 248] = z;
            p[tid + 496] = z;
            p[tid + 744] = z;
        }
        return;
    }

    // slow path: honest expansion from masks (rows with max<0.999 => mask 0)
    __shared__ int dt0[D_], dt1[D_];
    if (tid < D_) {
        float dl = delay_latent[tid];
        dt0[tid] = (int)floorf(fmaxf(dl, 0.0f));
        dt1[tid] = (int)floorf(fmaxf(-dl, 0.0f));
    }
    __syncthreads();

    const float w = *wptr;
    const bool hiHalf = (t >= 32);
    const int  sh = t & 31;

    if (tid < 248) {
#pragma unroll
        for (int k = 0; k < 16; ++k) {
            int cj = tid + k * 248;         // 0..3967
            int c = cj / 31;
            int j = cj - c * 31;
            int q0 = c * 2;
            unsigned m0 = 0u, m1 = 0u;
            if (g_rowmax[n][q0] >= 0.999f) {
                int d0 = min(dt0[j], g_clamp[n][q0]);
                m0 = hiHalf ? g_mhi[n][q0][d0] : g_mlo[n][q0][d0];
            }
            if (g_rowmax[n][q0 + 1] >= 0.999f) {
                int d1 = min(dt1[j], g_clamp[n][q0 + 1]);
                m1 = hiHalf ? g_mhi[n][q0 + 1][d1] : g_mlo[n][q0 + 1][d1];
            }
            int s = (int)((m0 >> sh) & 1u) + (int)((m1 >> sh) & 1u);
            obase[cj] = (float)s * w;       // exact for s in {0,1,2}
        }
    }
}

} // namespace

extern "C" void kernel_launch(void* const* d_in, const int* in_sizes, int n_in,
                              void* d_out, int out_size) {
    const float* x  = (const float*)d_in[0];   // (64,64,128,2)
    const float* dl = (const float*)d_in[1];   // (31,1)
    const float* w  = (const float*)d_in[2];   // scalar
    float* out = (float*)d_out;                // (64,64,128,31)
    analyze_kernel<<<256, 256>>>(x);
    write_kernel<<<4096, 256>>>(dl, w, out);
}